// round 4
// baseline (speedup 1.0000x reference)
#include <cuda_runtime.h>
#include <cstdint>

#define KK 16
#define BB 512
#define NP 4096
#define EPSF 1e-13f
#define TOLF 1.001e-5f   // np.isclose to 1.0: rtol(1e-5)*1.0 + atol(1e-8)

// packed labels: byte k of element n = c_in[n][k] (all < 32)
__device__ uint4 g_c8[NP];

__global__ void pack_labels_kernel(const int* __restrict__ c_in) {
    int t = blockIdx.x * blockDim.x + threadIdx.x;
    if (t < NP) {
        const int4* p = (const int4*)(c_in + t * KK);
        int4 a = p[0], b = p[1], c = p[2], d = p[3];
        uint4 r;
        r.x = (a.x & 255u) | ((a.y & 255u) << 8) | ((a.z & 255u) << 16) | ((a.w & 255u) << 24);
        r.y = (b.x & 255u) | ((b.y & 255u) << 8) | ((b.z & 255u) << 16) | ((b.w & 255u) << 24);
        r.z = (c.x & 255u) | ((c.y & 255u) << 8) | ((c.z & 255u) << 16) | ((c.w & 255u) << 24);
        r.w = (d.x & 255u) | ((d.y & 255u) << 8) | ((d.z & 255u) << 16) | ((d.w & 255u) << 24);
        g_c8[t] = r;
    }
}

__global__ __launch_bounds__(256, 5) void beran_kernel(
    const float* __restrict__ delta,
    const float* __restrict__ c_p,
    const float* __restrict__ bwp,
    float* __restrict__ out)
{
    __shared__ float w_sh[NP + 256];    // padded [256][17] floats, 17 KB
    __shared__ float s_score[KK * 32];  // 2 KB
    __shared__ float ws[8];
    __shared__ float s_tot_sh, g2_sh;

    const int tid  = threadIdx.x;
    const int lane = tid & 31;
    const int wid  = tid >> 5;          // 0..7
    const int b    = blockIdx.x;
    const unsigned FULL = 0xFFFFFFFFu;

    // ---- Phase A: softmax + score table. warp wid handles k=wid, wid+8 ----
    #pragma unroll
    for (int h = 0; h < 2; h++) {
        int k = wid + h * 8;
        float x = c_p[(k * BB + b) * 32 + lane];
        float m = x;
        #pragma unroll
        for (int d = 16; d; d >>= 1) m = fmaxf(m, __shfl_xor_sync(FULL, m, d));
        float e = __expf(x - m);
        float s = e;
        #pragma unroll
        for (int d = 16; d; d >>= 1) s += __shfl_xor_sync(FULL, s, d);
        float p = __fdividef(e, s);
        float ssq = p * p;
        #pragma unroll
        for (int d = 16; d; d >>= 1) ssq += __shfl_xor_sync(FULL, ssq, d);
        s_score[k * 32 + lane] = ssq - 2.0f * p + 1.0f;   // score[k][v]
    }
    __syncthreads();

    float sreg[KK];
    #pragma unroll
    for (int k = 0; k < KK; k++) sreg[k] = s_score[k * 32 + lane];

    const float bw = fminf(fmaxf(bwp[0], 0.1f), 10.0f);
    const float nib = -1.0f / bw;

    // ---- Phase B: coalesced gather (n = i*256 + tid); padded transpose store ----
    // store pos for n: row = n>>4, col = n&15, addr = row*17 + col
    const int base_w = (tid >> 4) * 17 + (tid & 15);
    #pragma unroll 4
    for (int i = 0; i < 16; i++) {
        uint4 pk = g_c8[i * 256 + tid];
        float m = 0.0f;
        // labels < 32 and shfl.idx uses b[4:0] only -> no masks needed
        m += __shfl_sync(FULL, sreg[0],  (int)pk.x);
        m += __shfl_sync(FULL, sreg[1],  (int)(pk.x >> 8));
        m += __shfl_sync(FULL, sreg[2],  (int)(pk.x >> 16));
        m += __shfl_sync(FULL, sreg[3],  (int)(pk.x >> 24));
        m += __shfl_sync(FULL, sreg[4],  (int)pk.y);
        m += __shfl_sync(FULL, sreg[5],  (int)(pk.y >> 8));
        m += __shfl_sync(FULL, sreg[6],  (int)(pk.y >> 16));
        m += __shfl_sync(FULL, sreg[7],  (int)(pk.y >> 24));
        m += __shfl_sync(FULL, sreg[8],  (int)pk.z);
        m += __shfl_sync(FULL, sreg[9],  (int)(pk.z >> 8));
        m += __shfl_sync(FULL, sreg[10], (int)(pk.z >> 16));
        m += __shfl_sync(FULL, sreg[11], (int)(pk.z >> 24));
        m += __shfl_sync(FULL, sreg[12], (int)pk.w);
        m += __shfl_sync(FULL, sreg[13], (int)(pk.w >> 8));
        m += __shfl_sync(FULL, sreg[14], (int)(pk.w >> 16));
        m += __shfl_sync(FULL, sreg[15], (int)(pk.w >> 24));
        w_sh[i * 272 + base_w] = __expf(m * nib);
    }
    __syncthreads();

    // ---- Phase C: scan #1 over w (16 contiguous elems/thread, padded reads) ----
    float o[16];
    {
        const int rbase = tid * 17;
        #pragma unroll
        for (int j = 0; j < 16; j++) o[j] = w_sh[rbase + j];
    }
    float tot = 0.0f;
    #pragma unroll
    for (int j = 0; j < 16; j++) tot += o[j];

    float ti = tot;
    #pragma unroll
    for (int d = 1; d < 32; d <<= 1) {
        float u = __shfl_up_sync(FULL, ti, d);
        if (lane >= d) ti += u;
    }
    if (lane == 31) ws[wid] = ti;
    __syncthreads();
    if (wid == 0) {
        float v = (lane < 8) ? ws[lane] : 0.0f;
        float vi = v;
        #pragma unroll
        for (int d = 1; d < 8; d <<= 1) {
            float u = __shfl_up_sync(FULL, vi, d);
            if (lane >= d) vi += u;
        }
        if (lane < 8) ws[lane] = vi - v;   // exclusive warp-prefix
        if (lane == 7) s_tot_sh = vi;      // grand total s
    }
    __syncthreads();

    const float off1  = ws[wid] + (ti - tot);   // exclusive prefix before my 16
    const float s_tot = s_tot_sh;
    // guard threshold on UNnormalized residual t = s - cum:  |1 - cum/s|<=TOL  <=>  |t|<=TOL*s
    const float tols = (s_tot < EPSF) ? 3.0e38f : TOLF * s_tot;

    // ---- Phase D/E: xi = log(t_prev / t), val = delta*xi; thread total ----
    float cum   = off1;
    float tprev = s_tot - off1;
    float tot2  = 0.0f;
    {
        const float4* dp = (const float4*)(delta + tid * 16);
        #pragma unroll
        for (int jc = 0; jc < 4; jc++) {
            float4 dv = dp[jc];
            #pragma unroll
            for (int l = 0; l < 4; l++) {
                int j = jc * 4 + l;
                float dl = (l == 0) ? dv.x : (l == 1) ? dv.y : (l == 2) ? dv.z : dv.w;
                cum += o[j];
                float t = s_tot - cum;
                bool bad = (fabsf(t) <= tols) || (fabsf(tprev) <= tols);
                float xi = bad ? 0.0f : __logf(__fdividef(tprev, t));
                float v = dl * xi;
                tot2 += v;
                o[j] = v;           // recycle: o -> val
                tprev = t;
            }
        }
    }

    // ---- scan #2 (hazards) ----
    float ti2 = tot2;
    #pragma unroll
    for (int d = 1; d < 32; d <<= 1) {
        float u = __shfl_up_sync(FULL, ti2, d);
        if (lane >= d) ti2 += u;
    }
    __syncthreads();   // off1/s_tot consumed; safe to reuse ws
    if (lane == 31) ws[wid] = ti2;
    __syncthreads();
    if (wid == 0) {
        float v = (lane < 8) ? ws[lane] : 0.0f;
        float vi = v;
        #pragma unroll
        for (int d = 1; d < 8; d <<= 1) {
            float u = __shfl_up_sync(FULL, vi, d);
            if (lane >= d) vi += u;
        }
        if (lane < 8) ws[lane] = vi - v;
        if (lane == 7) g2_sh = vi;          // grand total hazards
    }
    __syncthreads();
    const float off2 = ws[wid] + (ti2 - tot2);

    // s2 = sum(surv_steps) telescopes to 1 - surv[N-1]
    const float s2   = 1.0f - __expf(-g2_sh);
    const float inv2 = (s2 < EPSF) ? 0.0f : 1.0f / s2;
    float prev = (tid == 0) ? 1.0f : __expf(-off2);   // surv of element base-1

    // ---- Phase F: surv (write), steps (recycle val -> st), then write steps ----
    float h = off2;
    {
        float4* op = (float4*)(out + (size_t)b * NP + tid * 16);
        #pragma unroll
        for (int jc = 0; jc < 4; jc++) {
            float4 sv;
            #pragma unroll
            for (int l = 0; l < 4; l++) {
                int j = jc * 4 + l;
                h += o[j];
                float sj = __expf(-h);
                if (l == 0) sv.x = sj; else if (l == 1) sv.y = sj;
                else if (l == 2) sv.z = sj; else sv.w = sj;
                o[j] = prev - sj;   // recycle: val -> st
                prev = sj;
            }
            op[jc] = sv;
        }
    }
    {
        float4* op = (float4*)(out + (size_t)BB * NP + (size_t)b * NP + tid * 16);
        #pragma unroll
        for (int jc = 0; jc < 4; jc++) {
            op[jc] = make_float4(o[jc * 4] * inv2, o[jc * 4 + 1] * inv2,
                                 o[jc * 4 + 2] * inv2, o[jc * 4 + 3] * inv2);
        }
    }
}

extern "C" void kernel_launch(void* const* d_in, const int* in_sizes, int n_in,
                              void* d_out, int out_size) {
    const int*   c_in  = (const int*)d_in[0];
    const float* delta = (const float*)d_in[1];
    const float* c_p   = (const float*)d_in[2];
    const float* bwp   = (const float*)d_in[3];
    float* out = (float*)d_out;

    pack_labels_kernel<<<16, 256>>>(c_in);
    beran_kernel<<<BB, 256>>>(delta, c_p, bwp, out);
}